// round 1
// baseline (speedup 1.0000x reference)
#include <cuda_runtime.h>
#include <math.h>

#define EDIM 512
#define HEADS 8
#define DHD 64
#define KNN 32
#define NMAX 2048
#define CLAMPV 10000.0f

// ---- scratch (no allocations allowed) ----
__device__ float g_cent[NMAX * 3];
__device__ float g_pe[NMAX * EDIM];
__device__ float g_q[NMAX * EDIM];
__device__ float g_k[NMAX * EDIM];
__device__ float g_v[NMAX * EDIM];
__device__ float g_ctx[NMAX * EDIM];
__device__ int   g_topk[NMAX * KNN];

// ---------------------------------------------------------------------------
// 1) centroids of triangle faces: (N,9) -> (N,3), mean over 3 points
// ---------------------------------------------------------------------------
__global__ void centroid_kernel(const float* __restrict__ coords9,
                                float* __restrict__ cent, int N) {
    int i = blockIdx.x * blockDim.x + threadIdx.x;
    if (i >= N) return;
    const float inv3 = 1.0f / 3.0f;
#pragma unroll
    for (int c = 0; c < 3; c++) {
        float s = coords9[i * 9 + c] + coords9[i * 9 + 3 + c] + coords9[i * 9 + 6 + c];
        cent[i * 3 + c] = s * inv3;
    }
}

// ---------------------------------------------------------------------------
// 2) pos encoder (Linear(3,128) + exact GELU + LayerNorm(128)) and assembly of
//    pos_enhanced = concat(x + prompt [:,0:384], pos_enc) : (N,512)
//    One block of 128 threads per row.
// ---------------------------------------------------------------------------
__global__ void posenc_kernel(const float* __restrict__ x,
                              const float* __restrict__ prompt,
                              const float* __restrict__ cent,
                              const float* __restrict__ w1,   // (128,3)
                              const float* __restrict__ b1,   // (128,)
                              const float* __restrict__ lng,
                              const float* __restrict__ lnb,
                              float* __restrict__ pe, int N) {
    int i = blockIdx.x;
    int t = threadIdx.x;   // 0..127
    __shared__ float red[128];

    float cx = cent[i * 3 + 0], cy = cent[i * 3 + 1], cz = cent[i * 3 + 2];
    float h = cx * w1[t * 3 + 0] + cy * w1[t * 3 + 1] + cz * w1[t * 3 + 2] + b1[t];
    // exact GELU
    float gel = 0.5f * h * (1.0f + erff(h * 0.70710678118654752f));

    // mean
    red[t] = gel;
    __syncthreads();
    for (int s = 64; s > 0; s >>= 1) {
        if (t < s) red[t] += red[t + s];
        __syncthreads();
    }
    float mu = red[0] * (1.0f / 128.0f);
    __syncthreads();
    float d = gel - mu;
    red[t] = d * d;
    __syncthreads();
    for (int s = 64; s > 0; s >>= 1) {
        if (t < s) red[t] += red[t + s];
        __syncthreads();
    }
    float var = red[0] * (1.0f / 128.0f);
    float y = d * rsqrtf(var + 1e-5f) * lng[t] + lnb[t];

    pe[(size_t)i * EDIM + 384 + t] = y;
    // first 384 columns: x + prompt
    for (int c = t; c < 384; c += 128)
        pe[(size_t)i * EDIM + c] = x[(size_t)i * EDIM + c] + prompt[c];
}

// ---------------------------------------------------------------------------
// 3) per-row k-NN top-32 (smallest distance, tie-break lower index, matching
//    jax.lax.top_k stability). One block of 256 threads per row.
// ---------------------------------------------------------------------------
__global__ void topk_kernel(const float* __restrict__ cent,
                            int* __restrict__ topk, int N) {
    __shared__ float csx[NMAX], csy[NMAX], csz[NMAX];
    __shared__ float dist[NMAX];
    __shared__ float rmin[8];
    __shared__ int   rarg[8];

    int i = blockIdx.x;
    int t = threadIdx.x;
    int lane = t & 31, warp = t >> 5;

    for (int j = t; j < N; j += 256) {
        csx[j] = cent[j * 3 + 0];
        csy[j] = cent[j * 3 + 1];
        csz[j] = cent[j * 3 + 2];
    }
    __syncthreads();
    float xi = csx[i], yi = csy[i], zi = csz[i];
    for (int j = t; j < N; j += 256) {
        float dx = xi - csx[j], dy = yi - csy[j], dz = zi - csz[j];
        dist[j] = sqrtf(dx * dx + dy * dy + dz * dz);
    }
    __syncthreads();

    for (int r = 0; r < KNN; r++) {
        float best = INFINITY;
        int   barg = N;
        for (int j = t; j < N; j += 256) {
            float d = dist[j];
            if (d < best) { best = d; barg = j; }   // ascending j => lowest idx kept on tie
        }
#pragma unroll
        for (int off = 16; off; off >>= 1) {
            float ob = __shfl_xor_sync(0xffffffffu, best, off);
            int   oa = __shfl_xor_sync(0xffffffffu, barg, off);
            if (ob < best || (ob == best && oa < barg)) { best = ob; barg = oa; }
        }
        if (lane == 0) { rmin[warp] = best; rarg[warp] = barg; }
        __syncthreads();
        if (t == 0) {
            float fb = rmin[0]; int fa = rarg[0];
#pragma unroll
            for (int w = 1; w < 8; w++) {
                if (rmin[w] < fb || (rmin[w] == fb && rarg[w] < fa)) { fb = rmin[w]; fa = rarg[w]; }
            }
            topk[i * KNN + r] = fa;
            dist[fa] = INFINITY;
        }
        __syncthreads();
    }
}

// ---------------------------------------------------------------------------
// 4) GEMM: C[M,512] = A[M,512] @ B[512,512]^T + bias,  optional sanitize.
//    64x64 tile, 256 threads, 4x4 per thread, k-tile 16.
// ---------------------------------------------------------------------------
__global__ void gemm_abT_bias(const float* __restrict__ A,
                              const float* __restrict__ B,
                              const float* __restrict__ bias,
                              float* __restrict__ C,
                              int M, int Kd, int sanitize) {
    __shared__ float As[16][68];
    __shared__ float Bs[16][68];
    int tid = threadIdx.x;
    int tx = tid & 15, ty = tid >> 4;
    int bm = blockIdx.y * 64, bn = blockIdx.x * 64;
    int lr = tid >> 2;    // 0..63 : row within tile
    int lq = tid & 3;     // float4 chunk along k

    float acc[4][4];
#pragma unroll
    for (int a = 0; a < 4; a++)
#pragma unroll
        for (int b = 0; b < 4; b++) acc[a][b] = 0.0f;

    for (int kt = 0; kt < Kd; kt += 16) {
        int am = bm + lr;
        float4 av = make_float4(0.f, 0.f, 0.f, 0.f);
        if (am < M) av = *(const float4*)(A + (size_t)am * Kd + kt + lq * 4);
        As[lq * 4 + 0][lr] = av.x;
        As[lq * 4 + 1][lr] = av.y;
        As[lq * 4 + 2][lr] = av.z;
        As[lq * 4 + 3][lr] = av.w;

        int bnr = bn + lr;  // EDIM=512 divisible by 64, always in range
        float4 bv = *(const float4*)(B + (size_t)bnr * Kd + kt + lq * 4);
        Bs[lq * 4 + 0][lr] = bv.x;
        Bs[lq * 4 + 1][lr] = bv.y;
        Bs[lq * 4 + 2][lr] = bv.z;
        Bs[lq * 4 + 3][lr] = bv.w;
        __syncthreads();

#pragma unroll
        for (int kk = 0; kk < 16; kk++) {
            float4 a4 = *(const float4*)&As[kk][ty * 4];
            float4 b4 = *(const float4*)&Bs[kk][tx * 4];
            acc[0][0] += a4.x * b4.x; acc[0][1] += a4.x * b4.y;
            acc[0][2] += a4.x * b4.z; acc[0][3] += a4.x * b4.w;
            acc[1][0] += a4.y * b4.x; acc[1][1] += a4.y * b4.y;
            acc[1][2] += a4.y * b4.z; acc[1][3] += a4.y * b4.w;
            acc[2][0] += a4.z * b4.x; acc[2][1] += a4.z * b4.y;
            acc[2][2] += a4.z * b4.z; acc[2][3] += a4.z * b4.w;
            acc[3][0] += a4.w * b4.x; acc[3][1] += a4.w * b4.y;
            acc[3][2] += a4.w * b4.z; acc[3][3] += a4.w * b4.w;
        }
        __syncthreads();
    }

#pragma unroll
    for (int a = 0; a < 4; a++) {
        int m = bm + ty * 4 + a;
        if (m >= M) continue;
#pragma unroll
        for (int b = 0; b < 4; b++) {
            int n = bn + tx * 4 + b;
            float v = acc[a][b] + bias[n];
            if (sanitize) {
                if (isnan(v)) v = 0.0f;
                v = fminf(fmaxf(v, -CLAMPV), CLAMPV);
            }
            C[(size_t)m * EDIM + n] = v;
        }
    }
}

// ---------------------------------------------------------------------------
// 5) sparse gather attention: per query i, per head (one warp each),
//    softmax over the 32 top-k keys. Block = 256 threads (8 warps = 8 heads).
// ---------------------------------------------------------------------------
__global__ void attn_kernel(const float* __restrict__ q,
                            const float* __restrict__ k,
                            const float* __restrict__ v,
                            const int* __restrict__ topk,
                            float* __restrict__ ctx, int N) {
    int i = blockIdx.x;
    int lane = threadIdx.x & 31;
    int h = threadIdx.x >> 5;   // head 0..7
    __shared__ int idx_s[KNN];
    if (threadIdx.x < KNN) idx_s[threadIdx.x] = topk[i * KNN + threadIdx.x];
    __syncthreads();

    const float* qrow = q + (size_t)i * EDIM + h * DHD;
    float2 q2 = *(const float2*)(qrow + 2 * lane);

    float s_own = 0.0f;
#pragma unroll
    for (int j = 0; j < KNN; j++) {
        int m = idx_s[j];
        float2 k2 = *(const float2*)(k + (size_t)m * EDIM + h * DHD + 2 * lane);
        float p = q2.x * k2.x + q2.y * k2.y;
#pragma unroll
        for (int off = 16; off; off >>= 1) p += __shfl_xor_sync(0xffffffffu, p, off);
        if (lane == j) s_own = p * 0.125f;   // /sqrt(64)
    }
    // softmax across 32 lanes
    float mx = s_own;
#pragma unroll
    for (int off = 16; off; off >>= 1) mx = fmaxf(mx, __shfl_xor_sync(0xffffffffu, mx, off));
    float e = expf(s_own - mx);
    float sum = e;
#pragma unroll
    for (int off = 16; off; off >>= 1) sum += __shfl_xor_sync(0xffffffffu, sum, off);
    float p = e / sum;

    float2 acc = make_float2(0.f, 0.f);
#pragma unroll
    for (int j = 0; j < KNN; j++) {
        float pj = __shfl_sync(0xffffffffu, p, j);
        int m = idx_s[j];
        float2 v2 = *(const float2*)(v + (size_t)m * EDIM + h * DHD + 2 * lane);
        acc.x += pj * v2.x;
        acc.y += pj * v2.y;
    }
    *(float2*)(ctx + (size_t)i * EDIM + h * DHD + 2 * lane) = acc;
}

// ---------------------------------------------------------------------------
extern "C" void kernel_launch(void* const* d_in, const int* in_sizes, int n_in,
                              void* d_out, int out_size) {
    const float* x       = (const float*)d_in[0];
    const float* coords9 = (const float*)d_in[1];
    const float* prompt  = (const float*)d_in[2];
    const float* pw1     = (const float*)d_in[3];
    const float* pb1     = (const float*)d_in[4];
    const float* plng    = (const float*)d_in[5];
    const float* plnb    = (const float*)d_in[6];
    const float* wq      = (const float*)d_in[7];
    const float* wk      = (const float*)d_in[8];
    const float* wv      = (const float*)d_in[9];
    const float* bq      = (const float*)d_in[10];
    const float* bk      = (const float*)d_in[11];
    const float* bv      = (const float*)d_in[12];
    const float* wo      = (const float*)d_in[13];
    const float* bo      = (const float*)d_in[14];

    int N = in_sizes[1] / 9;

    float *cent, *pe, *qp, *kp, *vp, *ctx;
    int* tk;
    cudaGetSymbolAddress((void**)&cent, g_cent);
    cudaGetSymbolAddress((void**)&pe,   g_pe);
    cudaGetSymbolAddress((void**)&qp,   g_q);
    cudaGetSymbolAddress((void**)&kp,   g_k);
    cudaGetSymbolAddress((void**)&vp,   g_v);
    cudaGetSymbolAddress((void**)&ctx,  g_ctx);
    cudaGetSymbolAddress((void**)&tk,   g_topk);

    centroid_kernel<<<(N + 255) / 256, 256>>>(coords9, cent, N);
    posenc_kernel<<<N, 128>>>(x, prompt, cent, pw1, pb1, plng, plnb, pe, N);
    topk_kernel<<<N, 256>>>(cent, tk, N);

    dim3 gg(EDIM / 64, (N + 63) / 64);
    gemm_abT_bias<<<gg, 256>>>(pe, wq, bq, qp, N, EDIM, 0);
    gemm_abT_bias<<<gg, 256>>>(pe, wk, bk, kp, N, EDIM, 0);
    gemm_abT_bias<<<gg, 256>>>(pe, wv, bv, vp, N, EDIM, 0);

    attn_kernel<<<N, 256>>>(qp, kp, vp, tk, ctx, N);

    gemm_abT_bias<<<gg, 256>>>(ctx, wo, bo, (float*)d_out, N, EDIM, 1);
}